// round 13
// baseline (speedup 1.0000x reference)
#include <cuda_runtime.h>
#include <math.h>

// ISDALoss_EM on GB300 — round 13: k_fused D/U drops pack2 MOVs (ull2 L loads);
// k_yloss reads g_WT from global (no sWT staging), NB=8/YT=256/grid=256.
#define A_DIM 128
#define PITCH 132
#define MAX_S 512
#define MAX_N 4096
#define MAX_C 128

__device__ float g_WT[A_DIM * A_DIM];     // WT[i][c] = W[c][i]; c >= C zeroed
__device__ float g_D[MAX_S * A_DIM];
__device__ float g_U[MAX_S * A_DIM];
__device__ float g_score[MAX_N * 8];
__device__ int   g_labels[MAX_N];
__device__ int   g_ccount[MAX_C];
__device__ int   g_clist[(size_t)MAX_C * MAX_N];

__device__ __forceinline__ void fma2(unsigned long long& d, unsigned long long a,
                                     unsigned long long b) {
    asm("fma.rn.f32x2 %0, %1, %2, %0;" : "+l"(d) : "l"(a), "l"(b));
}
__device__ __forceinline__ unsigned long long pack2(float lo, float hi) {
    unsigned long long r;
    asm("mov.b64 %0, {%1,%2};" : "=l"(r) : "f"(lo), "f"(hi));
    return r;
}
__device__ __forceinline__ float2 unpack2(unsigned long long v) {
    float2 f;
    asm("mov.b64 {%0,%1}, %2;" : "=f"(f.x), "=f"(f.y) : "l"(v));
    return f;
}

// ---- W transpose (coalesced both ways) + zero g_ccount for k_labels --------
__global__ void k_wt(const float* __restrict__ W, int C) {
    __shared__ float tile[32][33];
    if (blockIdx.x == 0 && blockIdx.y == 0 && threadIdx.x < MAX_C)
        g_ccount[threadIdx.x] = 0;
    const int ct0 = blockIdx.x * 32;
    const int it0 = blockIdx.y * 32;
    const int tid = threadIdx.x;
    const int tr = tid >> 5, tc = tid & 31;
    #pragma unroll
    for (int r = 0; r < 32; r += 8) {
        int c = ct0 + tr + r;
        tile[tr + r][tc] = (c < C) ? W[(size_t)c * A_DIM + it0 + tc] : 0.0f;
    }
    __syncthreads();
    #pragma unroll
    for (int r = 0; r < 32; r += 8) {
        int i = it0 + tr + r;
        g_WT[(size_t)i * A_DIM + ct0 + tc] = tile[tc][tr + r];
    }
}

// labels: gridded; redundant detect for consistent dtype verdict.
__global__ void k_labels(const int* __restrict__ raw, int n,
                         float* out, int writeLoss) {
    const int tid = threadIdx.x;
    if (blockIdx.x == 0 && tid == 0 && writeLoss) out[0] = 0.0f;
    int nz = 0;
    for (int i = tid; i < n / 2; i += blockDim.x)
        nz |= (raw[2 * i + 1] != 0);
    const bool is32 = (__syncthreads_or(nz) != 0);
    const int stride = gridDim.x * blockDim.x;
    for (int i = blockIdx.x * blockDim.x + tid; i < n; i += stride) {
        int c = is32 ? raw[i] : raw[2 * i];
        g_labels[i] = c;
        int p = atomicAdd(&g_ccount[c], 1);
        g_clist[(size_t)c * MAX_N + p] = i;
    }
}

// ---- fused: v, blocked Cholesky, D/U, in-smem transpose, class solves -------
__global__ __launch_bounds__(256, 3)
void k_fused(const float* __restrict__ sigma, const float* __restrict__ W,
             const float* __restrict__ F, const float* __restrict__ mu,
             int C, int K) {
    extern __shared__ float sh[];
    float* sA  = sh;                       // 128 * 132
    float* swl = sA + A_DIM * PITCH;       // 128
    float* sv  = swl + A_DIM;              // 128
    float* srd = sv + A_DIM;               // 128
    float* sdg = srd + A_DIM;              // 128
    float* sD  = sdg + A_DIM;              // 128
    float* sU  = sD + A_DIM;               // 128
    __shared__ float slogdet;

    const int s = blockIdx.x;
    const int cls = s / K;
    const int kk = s - cls * K;
    const int tid = threadIdx.x;
    const int wid = tid >> 5, lane = tid & 31;

    // ---- load Sigma (float4, coalesced), w_l; zero sD ----
    {
        const float4* src4 = reinterpret_cast<const float4*>(sigma + (size_t)s * A_DIM * A_DIM);
        for (int idx = tid; idx < A_DIM * 32; idx += 256) {
            int i = idx >> 5, f = idx & 31;
            *reinterpret_cast<float4*>(&sA[i * PITCH + 4 * f]) = src4[idx];
        }
        if (tid < A_DIM) { swl[tid] = W[cls * A_DIM + tid]; sD[tid] = 0.0f; }
    }
    __syncthreads();

    // ---- v = Sigma @ w_l (before factorization) ----
    if (tid < A_DIM) {
        float acc = 0.0f;
        #pragma unroll 8
        for (int b = 0; b < A_DIM; ++b) acc += sA[b * PITCH + tid] * swl[b];
        sv[tid] = acc;
    }
    __syncthreads();

    // ---- blocked Cholesky (NB = 32) ----
    for (int kb = 0; kb < A_DIM; kb += 32) {
        if (wid == 0) {
            float m[32];
            float* row = &sA[(kb + lane) * PITCH + kb];
            #pragma unroll
            for (int c = 0; c < 32; ++c) m[c] = row[c];
            #pragma unroll
            for (int j = 0; j < 32; ++j) {
                float dj = __shfl_sync(0xffffffffu, m[j], j);
                float l = m[j] * rsqrtf(dj);
                m[j] = l;
                #pragma unroll
                for (int p = j + 1; p < 32; ++p)
                    m[p] -= l * __shfl_sync(0xffffffffu, l, p);
            }
            #pragma unroll
            for (int c = 0; c < 32; ++c)
                if (c <= lane) row[c] = m[c];
            srd[kb + lane] = 1.0f / m[lane];
            sdg[kb + lane] = m[lane];
        }
        __syncthreads();

        const int R = A_DIM - kb - 32;
        if (R > 0) {
            if (tid < R) {
                const int row = kb + 32 + tid;
                float* pr = &sA[row * PITCH + kb];
                const float* pd = &sA[kb * PITCH + kb];
                float x[32];
                #pragma unroll
                for (int c = 0; c < 32; ++c) x[c] = pr[c];
                #pragma unroll
                for (int j = 0; j < 32; ++j) {
                    float a = x[j];
                    #pragma unroll
                    for (int p = 0; p < j; ++p) a -= x[p] * pd[j * PITCH + p];
                    x[j] = a * srd[kb + j];
                }
                #pragma unroll
                for (int c = 0; c < 32; ++c) pr[c] = x[c];
            }
            __syncthreads();

            // SYRK: A22 -= L21 L21^T (lower), 8-col strips
            const int nb = R >> 5;
            const int ntask = 2 * nb * (nb + 1);
            for (int task = wid; task < ntask; task += 8) {
                int b = 0, t = task;
                while (t >= 4 * (b + 1)) { t -= 4 * (b + 1); ++b; }
                const int i  = kb + 32 + 32 * b + lane;
                const int j0 = kb + 32 + 8 * t;
                unsigned long long acc[8];
                #pragma unroll
                for (int q = 0; q < 8; ++q) acc[q] = 0ull;
                const float* pa = &sA[i * PITCH + kb];
                #pragma unroll
                for (int k = 0; k < 32; k += 4) {
                    ulonglong2 av = *reinterpret_cast<const ulonglong2*>(pa + k);
                    #pragma unroll
                    for (int q = 0; q < 8; ++q) {
                        ulonglong2 bv = *reinterpret_cast<const ulonglong2*>(
                            &sA[(j0 + q) * PITCH + kb + k]);
                        fma2(acc[q], av.x, bv.x);
                        fma2(acc[q], av.y, bv.y);
                    }
                }
                #pragma unroll
                for (int q = 0; q < 8; ++q) {
                    int col = j0 + q;
                    if (col <= i) {
                        float2 f = unpack2(acc[q]);
                        sA[i * PITCH + col] -= f.x + f.y;
                    }
                }
            }
            __syncthreads();
        }
    }

    // ---- zero upper triangle (needed by D/U ramp rows); logdet ----
    for (int idx = tid; idx < A_DIM * A_DIM; idx += 256) {
        int j = idx >> 7, i = idx & 127;
        if (i < j) sA[i * PITCH + j] = 0.0f;
    }
    if (tid < 32) {
        float v = logf(sdg[tid]) + logf(sdg[tid + 32]) +
                  logf(sdg[tid + 64]) + logf(sdg[tid + 96]);
        #pragma unroll
        for (int o = 16; o; o >>= 1) v += __shfl_xor_sync(0xffffffffu, v, o);
        if (tid == 0) slogdet = 2.0f * v;
    }
    __syncthreads();

    // ---- D_c = ||L^T w_c||^2 (register-tiled, packed-pair L loads),
    //      U_c = v . w_c ----
    for (int g = 0; g < 4; ++g) {
        const int t = (g & 1) ? (7 - wid) : wid;
        const int j0 = 16 * t;
        const int c = 32 * g + lane;
        unsigned long long acc[8];
        #pragma unroll
        for (int q = 0; q < 8; ++q) acc[q] = 0ull;
        float u = 0.0f;
        const bool doU = (t == 0);
        const float* wcol = g_WT + c;

        for (int i = j0; i < A_DIM; ++i) {
            const ulonglong2* Lr = reinterpret_cast<const ulonglong2*>(&sA[i * PITCH + j0]);
            ulonglong2 p0 = Lr[0];
            ulonglong2 p1 = Lr[1];
            ulonglong2 p2 = Lr[2];
            ulonglong2 p3 = Lr[3];
            float wv = wcol[i * A_DIM];
            unsigned long long w2 = pack2(wv, wv);
            fma2(acc[0], p0.x, w2);
            fma2(acc[1], p0.y, w2);
            fma2(acc[2], p1.x, w2);
            fma2(acc[3], p1.y, w2);
            fma2(acc[4], p2.x, w2);
            fma2(acc[5], p2.y, w2);
            fma2(acc[6], p3.x, w2);
            fma2(acc[7], p3.y, w2);
            if (doU) u += sv[i] * wv;
        }
        unsigned long long d2 = 0ull;
        #pragma unroll
        for (int q = 0; q < 8; ++q) fma2(d2, acc[q], acc[q]);
        float2 dd = unpack2(d2);
        atomicAdd(&sD[c], dd.x + dd.y);
        if (doU) sU[c] = u;
    }
    __syncthreads();

    for (int c = tid; c < C; c += 256) {
        g_D[s * A_DIM + c] = sD[c];
        g_U[s * A_DIM + c] = sU[c];
    }

    // ---- transpose lower -> upper (stale lower is dead in the solve) ----
    for (int idx = tid; idx < A_DIM * A_DIM; idx += 256) {
        int i = idx >> 7, j = idx & 127;
        if (i > j) sA[j * PITCH + i] = sA[i * PITCH + j];
    }
    __syncthreads();

    // ---- class-grouped solves: score = dist + logdet, 4 samples per warp ----
    const int cnt = g_ccount[cls];
    const float logd = slogdet;
    const float4* F4 = reinterpret_cast<const float4*>(F);
    const float4 mv = reinterpret_cast<const float4*>(mu)[(size_t)s * 32 + lane];

    for (int m0 = wid * 4; m0 < cnt; m0 += 32) {
        int n[4];
        bool has[4];
        #pragma unroll
        for (int r = 0; r < 4; ++r) {
            has[r] = (m0 + r) < cnt;
            n[r] = g_clist[(size_t)cls * MAX_N + (has[r] ? (m0 + r) : m0)];
        }
        float d[4][4], dist[4];
        #pragma unroll
        for (int r = 0; r < 4; ++r) {
            float4 fv = F4[(size_t)n[r] * 32 + lane];
            d[r][0] = fv.x - mv.x; d[r][1] = fv.y - mv.y;
            d[r][2] = fv.z - mv.z; d[r][3] = fv.w - mv.w;
            dist[r] = 0.0f;
        }
        #pragma unroll 4
        for (int j = 0; j < A_DIM; ++j) {
            float4 col = *reinterpret_cast<const float4*>(&sA[j * PITCH + 4 * lane]);
            float rdj = srd[j];
            int owner = j >> 2, q = j & 3;
            #pragma unroll
            for (int r = 0; r < 4; ++r) {
                float dq = (q == 0) ? d[r][0] : (q == 1) ? d[r][1]
                         : (q == 2) ? d[r][2] : d[r][3];
                float z = __shfl_sync(0xffffffffu, dq, owner) * rdj;
                dist[r] += z * z;
                d[r][0] -= col.x * z;
                d[r][1] -= col.y * z;
                d[r][2] -= col.z * z;
                d[r][3] -= col.w * z;
            }
        }
        if (lane == 0) {
            #pragma unroll
            for (int r = 0; r < 4; ++r)
                if (has[r]) g_score[n[r] * 8 + kk] = dist[r] + logd;
        }
    }
}

// ---------------- fused y = F W^T + b, argmin, aug, log-softmax, loss --------
// No W staging: GEMM reads pre-transposed g_WT from global (L1-resident).
#define NB 8
#define YT 256
__global__ __launch_bounds__(YT)
void k_yloss(const float* __restrict__ F,
             const float* __restrict__ bias, const float* __restrict__ ratioPtr,
             float* __restrict__ yout, float* __restrict__ lossout,
             int N, int C, int K, int writeLoss) {
    __shared__ float sF[NB * A_DIM];
    __shared__ float sY[NB * MAX_C];
    __shared__ float sB[MAX_C];
    const int tid = threadIdx.x;
    const int n0 = blockIdx.x * NB;

    for (int idx = tid; idx < NB * A_DIM; idx += YT) {
        int nl = idx >> 7;
        int n = n0 + nl;
        sF[idx] = (n < N) ? F[(size_t)n * A_DIM + (idx & 127)] : 0.0f;
    }
    if (tid < C) sB[tid] = bias[tid];
    __syncthreads();

    const int warp = tid >> 5, lane = tid & 31;
    const int nwarp = YT / 32;             // 8
    const int nchunk = (C + 31) >> 5;      // 4

    for (int task = warp; task < NB * nchunk; task += nwarp) {
        int nl = task / nchunk;
        int c = (task - nl * nchunk) * 32 + lane;
        int n = n0 + nl;
        if (c < C && n < N) {
            float acc = sB[c];
            const float* f = sF + nl * A_DIM;
            const float* wp = g_WT + c;
            #pragma unroll 4
            for (int aa = 0; aa < A_DIM; ++aa)
                acc += f[aa] * wp[aa * A_DIM];
            sY[nl * MAX_C + c] = acc;
            yout[(size_t)n * C + c] = acc;
        }
    }
    __syncthreads();

    // epilogue: warp nl handles sample nl; aug in place in sY
    const float hr = 0.5f * ratioPtr[0];
    const int nl = warp;
    const int n = n0 + nl;
    if (n < N) {
        int l = g_labels[n];
        const float* sc = g_score + n * 8;
        int k = 0;
        float best = sc[0];
        for (int kkk = 1; kkk < K; ++kkk) {
            float v = sc[kkk];
            if (v < best) { best = v; k = kkk; }
        }
        int s = l * K + k;
        const float* Dp = g_D + s * A_DIM;
        const float* Up = g_U + s * A_DIM;
        float ul = Up[l];
        float* aug = sY + nl * MAX_C;

        float mymax = -INFINITY;
        for (int m = 0; m < nchunk; ++m) {
            int c = lane + 32 * m;
            if (c < C) {
                float v = aug[c] + hr * (Dp[c] - 2.0f * Up[c] + ul);
                aug[c] = v;
                mymax = fmaxf(mymax, v);
            }
        }
        #pragma unroll
        for (int o = 16; o; o >>= 1)
            mymax = fmaxf(mymax, __shfl_xor_sync(0xffffffffu, mymax, o));
        __syncwarp();
        float sum = 0.0f;
        for (int m = 0; m < nchunk; ++m) {
            int c = lane + 32 * m;
            if (c < C) sum += expf(aug[c] - mymax);
        }
        #pragma unroll
        for (int o = 16; o; o >>= 1) sum += __shfl_xor_sync(0xffffffffu, sum, o);
        if (lane == 0 && writeLoss) {
            float lse = mymax + logf(sum);
            atomicAdd(lossout, (lse - aug[l]) / (float)N);
        }
    }
}

// ---------------- launch -----------------------------------------------------
extern "C" void kernel_launch(void* const* d_in, const int* in_sizes, int n_in,
                              void* d_out, int out_size) {
    const float* F     = (const float*)d_in[0];
    const float* W     = (const float*)d_in[1];
    const float* bias  = (const float*)d_in[2];
    const float* mu    = (const float*)d_in[4];
    const float* sigma = (const float*)d_in[5];
    const int*   lraw  = (const int*)d_in[6];
    const float* ratio = (const float*)d_in[7];

    const int C = in_sizes[2];
    const int K = in_sizes[3] / C;
    const int Ad = in_sizes[1] / C;
    const int N = in_sizes[0] / Ad;
    const int S = C * K;

    float* out = (float*)d_out;
    const int yoff = out_size - N * C;
    const int writeLoss = (yoff >= 1) ? 1 : 0;
    float* yout = out + (yoff > 0 ? yoff : 0);

    const int smem_fused = (A_DIM * PITCH + 6 * A_DIM) * 4;                // 70656

    cudaFuncSetAttribute(k_fused, cudaFuncAttributeMaxDynamicSharedMemorySize, smem_fused);

    dim3 wtgrid(4, 4);
    k_wt<<<wtgrid, 256>>>(W, C);                       // also zeroes g_ccount
    k_labels<<<16, 128>>>(lraw, N, out, writeLoss);
    k_fused<<<S, 256, smem_fused>>>(sigma, W, F, mu, C, K);
    k_yloss<<<(N + NB - 1) / NB, YT>>>(F, bias, ratio, yout, out,
                                       N, C, K, writeLoss);
}

// round 14
// speedup vs baseline: 1.0193x; 1.0193x over previous
#include <cuda_runtime.h>
#include <math.h>

// ISDALoss_EM on GB300 — round 14: best-of-breed recombination.
// k_fused/k_wt/k_labels = round 13 (ull2 D/U loads, −7us);
// k_yloss = round 12 verbatim (sWT staging, NB=16/YT=512, measured 19.97us).
#define A_DIM 128
#define PITCH 132
#define MAX_S 512
#define MAX_N 4096
#define MAX_C 128

__device__ float g_WT[A_DIM * A_DIM];     // WT[i][c] = W[c][i]; c >= C zeroed
__device__ float g_D[MAX_S * A_DIM];
__device__ float g_U[MAX_S * A_DIM];
__device__ float g_score[MAX_N * 8];
__device__ int   g_labels[MAX_N];
__device__ int   g_ccount[MAX_C];
__device__ int   g_clist[(size_t)MAX_C * MAX_N];

__device__ __forceinline__ void fma2(unsigned long long& d, unsigned long long a,
                                     unsigned long long b) {
    asm("fma.rn.f32x2 %0, %1, %2, %0;" : "+l"(d) : "l"(a), "l"(b));
}
__device__ __forceinline__ unsigned long long pack2(float lo, float hi) {
    unsigned long long r;
    asm("mov.b64 %0, {%1,%2};" : "=l"(r) : "f"(lo), "f"(hi));
    return r;
}
__device__ __forceinline__ float2 unpack2(unsigned long long v) {
    float2 f;
    asm("mov.b64 {%0,%1}, %2;" : "=f"(f.x), "=f"(f.y) : "l"(v));
    return f;
}

// ---- W transpose (coalesced both ways) + zero g_ccount for k_labels --------
__global__ void k_wt(const float* __restrict__ W, int C) {
    __shared__ float tile[32][33];
    if (blockIdx.x == 0 && blockIdx.y == 0 && threadIdx.x < MAX_C)
        g_ccount[threadIdx.x] = 0;
    const int ct0 = blockIdx.x * 32;
    const int it0 = blockIdx.y * 32;
    const int tid = threadIdx.x;
    const int tr = tid >> 5, tc = tid & 31;
    #pragma unroll
    for (int r = 0; r < 32; r += 8) {
        int c = ct0 + tr + r;
        tile[tr + r][tc] = (c < C) ? W[(size_t)c * A_DIM + it0 + tc] : 0.0f;
    }
    __syncthreads();
    #pragma unroll
    for (int r = 0; r < 32; r += 8) {
        int i = it0 + tr + r;
        g_WT[(size_t)i * A_DIM + ct0 + tc] = tile[tc][tr + r];
    }
}

// labels: gridded; redundant detect for consistent dtype verdict.
__global__ void k_labels(const int* __restrict__ raw, int n,
                         float* out, int writeLoss) {
    const int tid = threadIdx.x;
    if (blockIdx.x == 0 && tid == 0 && writeLoss) out[0] = 0.0f;
    int nz = 0;
    for (int i = tid; i < n / 2; i += blockDim.x)
        nz |= (raw[2 * i + 1] != 0);
    const bool is32 = (__syncthreads_or(nz) != 0);
    const int stride = gridDim.x * blockDim.x;
    for (int i = blockIdx.x * blockDim.x + tid; i < n; i += stride) {
        int c = is32 ? raw[i] : raw[2 * i];
        g_labels[i] = c;
        int p = atomicAdd(&g_ccount[c], 1);
        g_clist[(size_t)c * MAX_N + p] = i;
    }
}

// ---- fused: v, blocked Cholesky, D/U, in-smem transpose, class solves -------
__global__ __launch_bounds__(256, 3)
void k_fused(const float* __restrict__ sigma, const float* __restrict__ W,
             const float* __restrict__ F, const float* __restrict__ mu,
             int C, int K) {
    extern __shared__ float sh[];
    float* sA  = sh;                       // 128 * 132
    float* swl = sA + A_DIM * PITCH;       // 128
    float* sv  = swl + A_DIM;              // 128
    float* srd = sv + A_DIM;               // 128
    float* sdg = srd + A_DIM;              // 128
    float* sD  = sdg + A_DIM;              // 128
    float* sU  = sD + A_DIM;               // 128
    __shared__ float slogdet;

    const int s = blockIdx.x;
    const int cls = s / K;
    const int kk = s - cls * K;
    const int tid = threadIdx.x;
    const int wid = tid >> 5, lane = tid & 31;

    // ---- load Sigma (float4, coalesced), w_l; zero sD ----
    {
        const float4* src4 = reinterpret_cast<const float4*>(sigma + (size_t)s * A_DIM * A_DIM);
        for (int idx = tid; idx < A_DIM * 32; idx += 256) {
            int i = idx >> 5, f = idx & 31;
            *reinterpret_cast<float4*>(&sA[i * PITCH + 4 * f]) = src4[idx];
        }
        if (tid < A_DIM) { swl[tid] = W[cls * A_DIM + tid]; sD[tid] = 0.0f; }
    }
    __syncthreads();

    // ---- v = Sigma @ w_l (before factorization) ----
    if (tid < A_DIM) {
        float acc = 0.0f;
        #pragma unroll 8
        for (int b = 0; b < A_DIM; ++b) acc += sA[b * PITCH + tid] * swl[b];
        sv[tid] = acc;
    }
    __syncthreads();

    // ---- blocked Cholesky (NB = 32) ----
    for (int kb = 0; kb < A_DIM; kb += 32) {
        if (wid == 0) {
            float m[32];
            float* row = &sA[(kb + lane) * PITCH + kb];
            #pragma unroll
            for (int c = 0; c < 32; ++c) m[c] = row[c];
            #pragma unroll
            for (int j = 0; j < 32; ++j) {
                float dj = __shfl_sync(0xffffffffu, m[j], j);
                float l = m[j] * rsqrtf(dj);
                m[j] = l;
                #pragma unroll
                for (int p = j + 1; p < 32; ++p)
                    m[p] -= l * __shfl_sync(0xffffffffu, l, p);
            }
            #pragma unroll
            for (int c = 0; c < 32; ++c)
                if (c <= lane) row[c] = m[c];
            srd[kb + lane] = 1.0f / m[lane];
            sdg[kb + lane] = m[lane];
        }
        __syncthreads();

        const int R = A_DIM - kb - 32;
        if (R > 0) {
            if (tid < R) {
                const int row = kb + 32 + tid;
                float* pr = &sA[row * PITCH + kb];
                const float* pd = &sA[kb * PITCH + kb];
                float x[32];
                #pragma unroll
                for (int c = 0; c < 32; ++c) x[c] = pr[c];
                #pragma unroll
                for (int j = 0; j < 32; ++j) {
                    float a = x[j];
                    #pragma unroll
                    for (int p = 0; p < j; ++p) a -= x[p] * pd[j * PITCH + p];
                    x[j] = a * srd[kb + j];
                }
                #pragma unroll
                for (int c = 0; c < 32; ++c) pr[c] = x[c];
            }
            __syncthreads();

            // SYRK: A22 -= L21 L21^T (lower), 8-col strips
            const int nb = R >> 5;
            const int ntask = 2 * nb * (nb + 1);
            for (int task = wid; task < ntask; task += 8) {
                int b = 0, t = task;
                while (t >= 4 * (b + 1)) { t -= 4 * (b + 1); ++b; }
                const int i  = kb + 32 + 32 * b + lane;
                const int j0 = kb + 32 + 8 * t;
                unsigned long long acc[8];
                #pragma unroll
                for (int q = 0; q < 8; ++q) acc[q] = 0ull;
                const float* pa = &sA[i * PITCH + kb];
                #pragma unroll
                for (int k = 0; k < 32; k += 4) {
                    ulonglong2 av = *reinterpret_cast<const ulonglong2*>(pa + k);
                    #pragma unroll
                    for (int q = 0; q < 8; ++q) {
                        ulonglong2 bv = *reinterpret_cast<const ulonglong2*>(
                            &sA[(j0 + q) * PITCH + kb + k]);
                        fma2(acc[q], av.x, bv.x);
                        fma2(acc[q], av.y, bv.y);
                    }
                }
                #pragma unroll
                for (int q = 0; q < 8; ++q) {
                    int col = j0 + q;
                    if (col <= i) {
                        float2 f = unpack2(acc[q]);
                        sA[i * PITCH + col] -= f.x + f.y;
                    }
                }
            }
            __syncthreads();
        }
    }

    // ---- zero upper triangle; logdet ----
    for (int idx = tid; idx < A_DIM * A_DIM; idx += 256) {
        int j = idx >> 7, i = idx & 127;
        if (i < j) sA[i * PITCH + j] = 0.0f;
    }
    if (tid < 32) {
        float v = logf(sdg[tid]) + logf(sdg[tid + 32]) +
                  logf(sdg[tid + 64]) + logf(sdg[tid + 96]);
        #pragma unroll
        for (int o = 16; o; o >>= 1) v += __shfl_xor_sync(0xffffffffu, v, o);
        if (tid == 0) slogdet = 2.0f * v;
    }
    __syncthreads();

    // ---- D_c = ||L^T w_c||^2 (register-tiled, packed-pair L loads),
    //      U_c = v . w_c ----
    for (int g = 0; g < 4; ++g) {
        const int t = (g & 1) ? (7 - wid) : wid;
        const int j0 = 16 * t;
        const int c = 32 * g + lane;
        unsigned long long acc[8];
        #pragma unroll
        for (int q = 0; q < 8; ++q) acc[q] = 0ull;
        float u = 0.0f;
        const bool doU = (t == 0);
        const float* wcol = g_WT + c;

        for (int i = j0; i < A_DIM; ++i) {
            const ulonglong2* Lr = reinterpret_cast<const ulonglong2*>(&sA[i * PITCH + j0]);
            ulonglong2 p0 = Lr[0];
            ulonglong2 p1 = Lr[1];
            ulonglong2 p2 = Lr[2];
            ulonglong2 p3 = Lr[3];
            float wv = wcol[i * A_DIM];
            unsigned long long w2 = pack2(wv, wv);
            fma2(acc[0], p0.x, w2);
            fma2(acc[1], p0.y, w2);
            fma2(acc[2], p1.x, w2);
            fma2(acc[3], p1.y, w2);
            fma2(acc[4], p2.x, w2);
            fma2(acc[5], p2.y, w2);
            fma2(acc[6], p3.x, w2);
            fma2(acc[7], p3.y, w2);
            if (doU) u += sv[i] * wv;
        }
        unsigned long long d2 = 0ull;
        #pragma unroll
        for (int q = 0; q < 8; ++q) fma2(d2, acc[q], acc[q]);
        float2 dd = unpack2(d2);
        atomicAdd(&sD[c], dd.x + dd.y);
        if (doU) sU[c] = u;
    }
    __syncthreads();

    for (int c = tid; c < C; c += 256) {
        g_D[s * A_DIM + c] = sD[c];
        g_U[s * A_DIM + c] = sU[c];
    }

    // ---- transpose lower -> upper (stale lower is dead in the solve) ----
    for (int idx = tid; idx < A_DIM * A_DIM; idx += 256) {
        int i = idx >> 7, j = idx & 127;
        if (i > j) sA[j * PITCH + i] = sA[i * PITCH + j];
    }
    __syncthreads();

    // ---- class-grouped solves: score = dist + logdet, 4 samples per warp ----
    const int cnt = g_ccount[cls];
    const float logd = slogdet;
    const float4* F4 = reinterpret_cast<const float4*>(F);
    const float4 mv = reinterpret_cast<const float4*>(mu)[(size_t)s * 32 + lane];

    for (int m0 = wid * 4; m0 < cnt; m0 += 32) {
        int n[4];
        bool has[4];
        #pragma unroll
        for (int r = 0; r < 4; ++r) {
            has[r] = (m0 + r) < cnt;
            n[r] = g_clist[(size_t)cls * MAX_N + (has[r] ? (m0 + r) : m0)];
        }
        float d[4][4], dist[4];
        #pragma unroll
        for (int r = 0; r < 4; ++r) {
            float4 fv = F4[(size_t)n[r] * 32 + lane];
            d[r][0] = fv.x - mv.x; d[r][1] = fv.y - mv.y;
            d[r][2] = fv.z - mv.z; d[r][3] = fv.w - mv.w;
            dist[r] = 0.0f;
        }
        #pragma unroll 4
        for (int j = 0; j < A_DIM; ++j) {
            float4 col = *reinterpret_cast<const float4*>(&sA[j * PITCH + 4 * lane]);
            float rdj = srd[j];
            int owner = j >> 2, q = j & 3;
            #pragma unroll
            for (int r = 0; r < 4; ++r) {
                float dq = (q == 0) ? d[r][0] : (q == 1) ? d[r][1]
                         : (q == 2) ? d[r][2] : d[r][3];
                float z = __shfl_sync(0xffffffffu, dq, owner) * rdj;
                dist[r] += z * z;
                d[r][0] -= col.x * z;
                d[r][1] -= col.y * z;
                d[r][2] -= col.z * z;
                d[r][3] -= col.w * z;
            }
        }
        if (lane == 0) {
            #pragma unroll
            for (int r = 0; r < 4; ++r)
                if (has[r]) g_score[n[r] * 8 + kk] = dist[r] + logd;
        }
    }
}

// ---------------- fused y = F W^T + b, argmin, aug, log-softmax, loss --------
// Round-12 verbatim: sWT staging, unroll-limited GEMM, in-place aug (19.97us).
#define NB 16
#define YT 512
__global__ __launch_bounds__(YT)
void k_yloss(const float* __restrict__ F, const float* __restrict__ W,
             const float* __restrict__ bias, const float* __restrict__ ratioPtr,
             float* __restrict__ yout, float* __restrict__ lossout,
             int N, int C, int K, int writeLoss) {
    extern __shared__ float sh[];
    float* sWT = sh;                       // [128][C]
    float* sF  = sWT + A_DIM * C;          // [NB][128]
    float* sY  = sF + NB * A_DIM;          // [NB][C]  (y, then aug in place)
    float* sB  = sY + NB * C;              // [C]
    const int tid = threadIdx.x;
    const int n0 = blockIdx.x * NB;

    for (int idx = tid; idx < C * A_DIM; idx += YT) {
        int c = idx >> 7, aa = idx & 127;
        sWT[aa * C + c] = W[idx];
    }
    for (int idx = tid; idx < NB * A_DIM; idx += YT) {
        int nl = idx >> 7;
        int n = n0 + nl;
        sF[idx] = (n < N) ? F[(size_t)n * A_DIM + (idx & 127)] : 0.0f;
    }
    for (int c = tid; c < C; c += YT) sB[c] = bias[c];
    __syncthreads();

    const int warp = tid >> 5, lane = tid & 31;
    const int nwarp = YT / 32;             // 16
    const int nchunk = (C + 31) >> 5;

    for (int task = warp; task < NB * nchunk; task += nwarp) {
        int nl = task / nchunk;
        int c = (task - nl * nchunk) * 32 + lane;
        int n = n0 + nl;
        if (c < C && n < N) {
            float acc = sB[c];
            const float* f = sF + nl * A_DIM;
            #pragma unroll 1
            for (int aa = 0; aa < A_DIM; aa += 16) {
                #pragma unroll
                for (int q = 0; q < 16; q += 4) {
                    float4 fv = *reinterpret_cast<const float4*>(f + aa + q);
                    acc += fv.x * sWT[(aa + q) * C + c];
                    acc += fv.y * sWT[(aa + q + 1) * C + c];
                    acc += fv.z * sWT[(aa + q + 2) * C + c];
                    acc += fv.w * sWT[(aa + q + 3) * C + c];
                }
            }
            sY[nl * C + c] = acc;
            yout[(size_t)n * C + c] = acc;
        }
    }
    __syncthreads();

    // epilogue: warp nl handles sample nl; aug written in place in sY
    const float hr = 0.5f * ratioPtr[0];
    const int nl = warp;
    const int n = n0 + nl;
    if (n < N) {
        int l = g_labels[n];
        const float* sc = g_score + n * 8;
        int k = 0;
        float best = sc[0];
        for (int kkk = 1; kkk < K; ++kkk) {
            float v = sc[kkk];
            if (v < best) { best = v; k = kkk; }
        }
        int s = l * K + k;
        const float* Dp = g_D + s * A_DIM;
        const float* Up = g_U + s * A_DIM;
        float ul = Up[l];
        float* aug = sY + nl * C;

        float mymax = -INFINITY;
        for (int m = 0; m < nchunk; ++m) {
            int c = lane + 32 * m;
            if (c < C) {
                float v = aug[c] + hr * (Dp[c] - 2.0f * Up[c] + ul);
                aug[c] = v;
                mymax = fmaxf(mymax, v);
            }
        }
        #pragma unroll
        for (int o = 16; o; o >>= 1)
            mymax = fmaxf(mymax, __shfl_xor_sync(0xffffffffu, mymax, o));
        __syncwarp();
        float sum = 0.0f;
        for (int m = 0; m < nchunk; ++m) {
            int c = lane + 32 * m;
            if (c < C) sum += expf(aug[c] - mymax);
        }
        #pragma unroll
        for (int o = 16; o; o >>= 1) sum += __shfl_xor_sync(0xffffffffu, sum, o);
        if (lane == 0 && writeLoss) {
            float lse = mymax + logf(sum);
            atomicAdd(lossout, (lse - aug[l]) / (float)N);
        }
    }
}

// ---------------- launch -----------------------------------------------------
extern "C" void kernel_launch(void* const* d_in, const int* in_sizes, int n_in,
                              void* d_out, int out_size) {
    const float* F     = (const float*)d_in[0];
    const float* W     = (const float*)d_in[1];
    const float* bias  = (const float*)d_in[2];
    const float* mu    = (const float*)d_in[4];
    const float* sigma = (const float*)d_in[5];
    const int*   lraw  = (const int*)d_in[6];
    const float* ratio = (const float*)d_in[7];

    const int C = in_sizes[2];
    const int K = in_sizes[3] / C;
    const int Ad = in_sizes[1] / C;
    const int N = in_sizes[0] / Ad;
    const int S = C * K;

    float* out = (float*)d_out;
    const int yoff = out_size - N * C;
    const int writeLoss = (yoff >= 1) ? 1 : 0;
    float* yout = out + (yoff > 0 ? yoff : 0);

    const int smem_fused = (A_DIM * PITCH + 6 * A_DIM) * 4;                // 70656
    const int smem_yl    = (A_DIM * C + NB * A_DIM + NB * C + C) * 4;      // 66192

    cudaFuncSetAttribute(k_fused, cudaFuncAttributeMaxDynamicSharedMemorySize, smem_fused);
    cudaFuncSetAttribute(k_yloss, cudaFuncAttributeMaxDynamicSharedMemorySize, smem_yl);

    dim3 wtgrid(4, 4);
    k_wt<<<wtgrid, 256>>>(W, C);                       // also zeroes g_ccount
    k_labels<<<16, 128>>>(lraw, N, out, writeLoss);
    k_fused<<<S, 256, smem_fused>>>(sigma, W, F, mu, C, K);
    k_yloss<<<(N + NB - 1) / NB, YT, smem_yl>>>(F, W, bias, ratio, yout, out,
                                                N, C, K, writeLoss);
}

// round 15
// speedup vs baseline: 1.0242x; 1.0048x over previous
#include <cuda_runtime.h>
#include <math.h>

// ISDALoss_EM on GB300 — round 15: heterogeneous mega-kernel. 128 y-GEMM blocks
// (independent of fused work) share the grid with 400 fused blocks, absorbing
// the y GEMM into k_fused's latency slack. Epilogue split into tiny k_loss.
#define A_DIM 128
#define PITCH 132
#define MAX_S 512
#define MAX_N 4096
#define MAX_C 128

__device__ float g_WT[A_DIM * A_DIM];     // WT[i][c] = W[c][i]; c >= C zeroed
__device__ float g_D[MAX_S * A_DIM];
__device__ float g_U[MAX_S * A_DIM];
__device__ float g_score[MAX_N * 8];
__device__ int   g_labels[MAX_N];
__device__ int   g_ccount[MAX_C];
__device__ int   g_clist[(size_t)MAX_C * MAX_N];

__device__ __forceinline__ void fma2(unsigned long long& d, unsigned long long a,
                                     unsigned long long b) {
    asm("fma.rn.f32x2 %0, %1, %2, %0;" : "+l"(d) : "l"(a), "l"(b));
}
__device__ __forceinline__ unsigned long long pack2(float lo, float hi) {
    unsigned long long r;
    asm("mov.b64 %0, {%1,%2};" : "=l"(r) : "f"(lo), "f"(hi));
    return r;
}
__device__ __forceinline__ float2 unpack2(unsigned long long v) {
    float2 f;
    asm("mov.b64 {%0,%1}, %2;" : "=f"(f.x), "=f"(f.y) : "l"(v));
    return f;
}

// ---- W transpose (coalesced both ways) + zero g_ccount for k_labels --------
__global__ void k_wt(const float* __restrict__ W, int C) {
    __shared__ float tile[32][33];
    if (blockIdx.x == 0 && blockIdx.y == 0 && threadIdx.x < MAX_C)
        g_ccount[threadIdx.x] = 0;
    const int ct0 = blockIdx.x * 32;
    const int it0 = blockIdx.y * 32;
    const int tid = threadIdx.x;
    const int tr = tid >> 5, tc = tid & 31;
    #pragma unroll
    for (int r = 0; r < 32; r += 8) {
        int c = ct0 + tr + r;
        tile[tr + r][tc] = (c < C) ? W[(size_t)c * A_DIM + it0 + tc] : 0.0f;
    }
    __syncthreads();
    #pragma unroll
    for (int r = 0; r < 32; r += 8) {
        int i = it0 + tr + r;
        g_WT[(size_t)i * A_DIM + ct0 + tc] = tile[tc][tr + r];
    }
}

// labels: gridded; redundant detect for consistent dtype verdict.
__global__ void k_labels(const int* __restrict__ raw, int n,
                         float* out, int writeLoss) {
    const int tid = threadIdx.x;
    if (blockIdx.x == 0 && tid == 0 && writeLoss) out[0] = 0.0f;
    int nz = 0;
    for (int i = tid; i < n / 2; i += blockDim.x)
        nz |= (raw[2 * i + 1] != 0);
    const bool is32 = (__syncthreads_or(nz) != 0);
    const int stride = gridDim.x * blockDim.x;
    for (int i = blockIdx.x * blockDim.x + tid; i < n; i += stride) {
        int c = is32 ? raw[i] : raw[2 * i];
        g_labels[i] = c;
        int p = atomicAdd(&g_ccount[c], 1);
        g_clist[(size_t)c * MAX_N + p] = i;
    }
}

// ---- mega: y-GEMM blocks (idx < YB) + fused sigma blocks (idx >= YB) --------
#define YNB 16
__global__ __launch_bounds__(256, 3)
void k_mega(const float* __restrict__ sigma, const float* __restrict__ W,
            const float* __restrict__ F, const float* __restrict__ mu,
            const float* __restrict__ bias, float* __restrict__ yout,
            int C, int K, int N, int YB) {
    extern __shared__ float sh[];
    const int tid = threadIdx.x;
    const int wid = tid >> 5, lane = tid & 31;

    if (blockIdx.x < YB) {
        // ================= y-GEMM block: y = F W^T + b for 16 samples ========
        float* sWT = sh;                    // [128][C]
        float* sF  = sWT + A_DIM * C;       // [YNB][128]
        float* sB  = sF + YNB * A_DIM;      // [C]
        const int n0 = blockIdx.x * YNB;

        for (int idx = tid; idx < C * A_DIM; idx += 256) {
            int c = idx >> 7, aa = idx & 127;
            sWT[aa * C + c] = W[idx];
        }
        for (int idx = tid; idx < YNB * A_DIM; idx += 256) {
            int nl = idx >> 7;
            int n = n0 + nl;
            sF[idx] = (n < N) ? F[(size_t)n * A_DIM + (idx & 127)] : 0.0f;
        }
        for (int c = tid; c < C; c += 256) sB[c] = bias[c];
        __syncthreads();

        const int nchunk = (C + 31) >> 5;
        for (int task = wid; task < YNB * nchunk; task += 8) {
            int nl = task / nchunk;
            int c = (task - nl * nchunk) * 32 + lane;
            int n = n0 + nl;
            if (c < C && n < N) {
                float acc = sB[c];
                const float* f = sF + nl * A_DIM;
                #pragma unroll 1
                for (int aa = 0; aa < A_DIM; aa += 16) {
                    #pragma unroll
                    for (int q = 0; q < 16; q += 4) {
                        float4 fv = *reinterpret_cast<const float4*>(f + aa + q);
                        acc += fv.x * sWT[(aa + q) * C + c];
                        acc += fv.y * sWT[(aa + q + 1) * C + c];
                        acc += fv.z * sWT[(aa + q + 2) * C + c];
                        acc += fv.w * sWT[(aa + q + 3) * C + c];
                    }
                }
                yout[(size_t)n * C + c] = acc;
            }
        }
        return;
    }

    // ================= fused sigma block (byte-identical math) ===============
    float* sA  = sh;                       // 128 * 132
    float* swl = sA + A_DIM * PITCH;       // 128
    float* sv  = swl + A_DIM;              // 128
    float* srd = sv + A_DIM;               // 128
    float* sdg = srd + A_DIM;              // 128
    float* sD  = sdg + A_DIM;              // 128
    float* sU  = sD + A_DIM;               // 128
    __shared__ float slogdet;

    const int s = blockIdx.x - YB;
    const int cls = s / K;
    const int kk = s - cls * K;

    // ---- load Sigma (float4, coalesced), w_l; zero sD ----
    {
        const float4* src4 = reinterpret_cast<const float4*>(sigma + (size_t)s * A_DIM * A_DIM);
        for (int idx = tid; idx < A_DIM * 32; idx += 256) {
            int i = idx >> 5, f = idx & 31;
            *reinterpret_cast<float4*>(&sA[i * PITCH + 4 * f]) = src4[idx];
        }
        if (tid < A_DIM) { swl[tid] = W[cls * A_DIM + tid]; sD[tid] = 0.0f; }
    }
    __syncthreads();

    // ---- v = Sigma @ w_l (before factorization) ----
    if (tid < A_DIM) {
        float acc = 0.0f;
        #pragma unroll 8
        for (int b = 0; b < A_DIM; ++b) acc += sA[b * PITCH + tid] * swl[b];
        sv[tid] = acc;
    }
    __syncthreads();

    // ---- blocked Cholesky (NB = 32) ----
    for (int kb = 0; kb < A_DIM; kb += 32) {
        if (wid == 0) {
            float m[32];
            float* row = &sA[(kb + lane) * PITCH + kb];
            #pragma unroll
            for (int c = 0; c < 32; ++c) m[c] = row[c];
            #pragma unroll
            for (int j = 0; j < 32; ++j) {
                float dj = __shfl_sync(0xffffffffu, m[j], j);
                float l = m[j] * rsqrtf(dj);
                m[j] = l;
                #pragma unroll
                for (int p = j + 1; p < 32; ++p)
                    m[p] -= l * __shfl_sync(0xffffffffu, l, p);
            }
            #pragma unroll
            for (int c = 0; c < 32; ++c)
                if (c <= lane) row[c] = m[c];
            srd[kb + lane] = 1.0f / m[lane];
            sdg[kb + lane] = m[lane];
        }
        __syncthreads();

        const int R = A_DIM - kb - 32;
        if (R > 0) {
            if (tid < R) {
                const int row = kb + 32 + tid;
                float* pr = &sA[row * PITCH + kb];
                const float* pd = &sA[kb * PITCH + kb];
                float x[32];
                #pragma unroll
                for (int c = 0; c < 32; ++c) x[c] = pr[c];
                #pragma unroll
                for (int j = 0; j < 32; ++j) {
                    float a = x[j];
                    #pragma unroll
                    for (int p = 0; p < j; ++p) a -= x[p] * pd[j * PITCH + p];
                    x[j] = a * srd[kb + j];
                }
                #pragma unroll
                for (int c = 0; c < 32; ++c) pr[c] = x[c];
            }
            __syncthreads();

            // SYRK: A22 -= L21 L21^T (lower), 8-col strips
            const int nb = R >> 5;
            const int ntask = 2 * nb * (nb + 1);
            for (int task = wid; task < ntask; task += 8) {
                int b = 0, t = task;
                while (t >= 4 * (b + 1)) { t -= 4 * (b + 1); ++b; }
                const int i  = kb + 32 + 32 * b + lane;
                const int j0 = kb + 32 + 8 * t;
                unsigned long long acc[8];
                #pragma unroll
                for (int q = 0; q < 8; ++q) acc[q] = 0ull;
                const float* pa = &sA[i * PITCH + kb];
                #pragma unroll
                for (int k = 0; k < 32; k += 4) {
                    ulonglong2 av = *reinterpret_cast<const ulonglong2*>(pa + k);
                    #pragma unroll
                    for (int q = 0; q < 8; ++q) {
                        ulonglong2 bv = *reinterpret_cast<const ulonglong2*>(
                            &sA[(j0 + q) * PITCH + kb + k]);
                        fma2(acc[q], av.x, bv.x);
                        fma2(acc[q], av.y, bv.y);
                    }
                }
                #pragma unroll
                for (int q = 0; q < 8; ++q) {
                    int col = j0 + q;
                    if (col <= i) {
                        float2 f = unpack2(acc[q]);
                        sA[i * PITCH + col] -= f.x + f.y;
                    }
                }
            }
            __syncthreads();
        }
    }

    // ---- zero upper triangle; logdet ----
    for (int idx = tid; idx < A_DIM * A_DIM; idx += 256) {
        int j = idx >> 7, i = idx & 127;
        if (i < j) sA[i * PITCH + j] = 0.0f;
    }
    if (tid < 32) {
        float v = logf(sdg[tid]) + logf(sdg[tid + 32]) +
                  logf(sdg[tid + 64]) + logf(sdg[tid + 96]);
        #pragma unroll
        for (int o = 16; o; o >>= 1) v += __shfl_xor_sync(0xffffffffu, v, o);
        if (tid == 0) slogdet = 2.0f * v;
    }
    __syncthreads();

    // ---- D_c = ||L^T w_c||^2, U_c = v . w_c ----
    for (int g = 0; g < 4; ++g) {
        const int t = (g & 1) ? (7 - wid) : wid;
        const int j0 = 16 * t;
        const int c = 32 * g + lane;
        unsigned long long acc[8];
        #pragma unroll
        for (int q = 0; q < 8; ++q) acc[q] = 0ull;
        float u = 0.0f;
        const bool doU = (t == 0);
        const float* wcol = g_WT + c;

        for (int i = j0; i < A_DIM; ++i) {
            const ulonglong2* Lr = reinterpret_cast<const ulonglong2*>(&sA[i * PITCH + j0]);
            ulonglong2 p0 = Lr[0];
            ulonglong2 p1 = Lr[1];
            ulonglong2 p2 = Lr[2];
            ulonglong2 p3 = Lr[3];
            float wv = wcol[i * A_DIM];
            unsigned long long w2 = pack2(wv, wv);
            fma2(acc[0], p0.x, w2);
            fma2(acc[1], p0.y, w2);
            fma2(acc[2], p1.x, w2);
            fma2(acc[3], p1.y, w2);
            fma2(acc[4], p2.x, w2);
            fma2(acc[5], p2.y, w2);
            fma2(acc[6], p3.x, w2);
            fma2(acc[7], p3.y, w2);
            if (doU) u += sv[i] * wv;
        }
        unsigned long long d2 = 0ull;
        #pragma unroll
        for (int q = 0; q < 8; ++q) fma2(d2, acc[q], acc[q]);
        float2 dd = unpack2(d2);
        atomicAdd(&sD[c], dd.x + dd.y);
        if (doU) sU[c] = u;
    }
    __syncthreads();

    for (int c = tid; c < C; c += 256) {
        g_D[s * A_DIM + c] = sD[c];
        g_U[s * A_DIM + c] = sU[c];
    }

    // ---- transpose lower -> upper (stale lower is dead in the solve) ----
    for (int idx = tid; idx < A_DIM * A_DIM; idx += 256) {
        int i = idx >> 7, j = idx & 127;
        if (i > j) sA[j * PITCH + i] = sA[i * PITCH + j];
    }
    __syncthreads();

    // ---- class-grouped solves: score = dist + logdet, 4 samples per warp ----
    const int cnt = g_ccount[cls];
    const float logd = slogdet;
    const float4* F4 = reinterpret_cast<const float4*>(F);
    const float4 mv = reinterpret_cast<const float4*>(mu)[(size_t)s * 32 + lane];

    for (int m0 = wid * 4; m0 < cnt; m0 += 32) {
        int n[4];
        bool has[4];
        #pragma unroll
        for (int r = 0; r < 4; ++r) {
            has[r] = (m0 + r) < cnt;
            n[r] = g_clist[(size_t)cls * MAX_N + (has[r] ? (m0 + r) : m0)];
        }
        float d[4][4], dist[4];
        #pragma unroll
        for (int r = 0; r < 4; ++r) {
            float4 fv = F4[(size_t)n[r] * 32 + lane];
            d[r][0] = fv.x - mv.x; d[r][1] = fv.y - mv.y;
            d[r][2] = fv.z - mv.z; d[r][3] = fv.w - mv.w;
            dist[r] = 0.0f;
        }
        #pragma unroll 4
        for (int j = 0; j < A_DIM; ++j) {
            float4 col = *reinterpret_cast<const float4*>(&sA[j * PITCH + 4 * lane]);
            float rdj = srd[j];
            int owner = j >> 2, q = j & 3;
            #pragma unroll
            for (int r = 0; r < 4; ++r) {
                float dq = (q == 0) ? d[r][0] : (q == 1) ? d[r][1]
                         : (q == 2) ? d[r][2] : d[r][3];
                float z = __shfl_sync(0xffffffffu, dq, owner) * rdj;
                dist[r] += z * z;
                d[r][0] -= col.x * z;
                d[r][1] -= col.y * z;
                d[r][2] -= col.z * z;
                d[r][3] -= col.w * z;
            }
        }
        if (lane == 0) {
            #pragma unroll
            for (int r = 0; r < 4; ++r)
                if (has[r]) g_score[n[r] * 8 + kk] = dist[r] + logd;
        }
    }
}

// ---- epilogue: per-sample argmin, aug, log-softmax, loss (warp per sample) --
__global__ __launch_bounds__(256)
void k_loss(const float* __restrict__ yv, const float* __restrict__ ratioPtr,
            float* __restrict__ lossout, int N, int C, int K) {
    const int warp = threadIdx.x >> 5, lane = threadIdx.x & 31;
    const int n = blockIdx.x * 8 + warp;
    if (n >= N) return;
    const float hr = 0.5f * ratioPtr[0];
    const int l = g_labels[n];
    const float* sc = g_score + n * 8;
    int k = 0;
    float best = sc[0];
    for (int kk = 1; kk < K; ++kk) {
        float v = sc[kk];
        if (v < best) { best = v; k = kk; }
    }
    const int s = l * K + k;
    const float* Dp = g_D + s * A_DIM;
    const float* Up = g_U + s * A_DIM;
    const float ul = Up[l];
    const float* yrow = yv + (size_t)n * C;
    const int nchunk = (C + 31) >> 5;

    float augv[4];
    float mymax = -INFINITY;
    #pragma unroll
    for (int m = 0; m < 4; ++m) {
        int c = lane + 32 * m;
        float v = -INFINITY;
        if (m < nchunk && c < C)
            v = yrow[c] + hr * (Dp[c] - 2.0f * Up[c] + ul);
        augv[m] = v;
        mymax = fmaxf(mymax, v);
    }
    #pragma unroll
    for (int o = 16; o; o >>= 1)
        mymax = fmaxf(mymax, __shfl_xor_sync(0xffffffffu, mymax, o));
    float sum = 0.0f;
    #pragma unroll
    for (int m = 0; m < 4; ++m) {
        int c = lane + 32 * m;
        if (m < nchunk && c < C) sum += expf(augv[m] - mymax);
    }
    #pragma unroll
    for (int o = 16; o; o >>= 1) sum += __shfl_xor_sync(0xffffffffu, sum, o);
    if (lane == 0) {
        float lse = mymax + logf(sum);
        float aug_l = yrow[l] + hr * (Dp[l] - Up[l]);
        atomicAdd(lossout, (lse - aug_l) / (float)N);
    }
}

// ---------------- launch -----------------------------------------------------
extern "C" void kernel_launch(void* const* d_in, const int* in_sizes, int n_in,
                              void* d_out, int out_size) {
    const float* F     = (const float*)d_in[0];
    const float* W     = (const float*)d_in[1];
    const float* bias  = (const float*)d_in[2];
    const float* mu    = (const float*)d_in[4];
    const float* sigma = (const float*)d_in[5];
    const int*   lraw  = (const int*)d_in[6];
    const float* ratio = (const float*)d_in[7];

    const int C = in_sizes[2];
    const int K = in_sizes[3] / C;
    const int Ad = in_sizes[1] / C;
    const int N = in_sizes[0] / Ad;
    const int S = C * K;
    const int YB = (N + YNB - 1) / YNB;

    float* out = (float*)d_out;
    const int yoff = out_size - N * C;
    const int writeLoss = (yoff >= 1) ? 1 : 0;
    float* yout = out + (yoff > 0 ? yoff : 0);

    const int smem_fused = (A_DIM * PITCH + 6 * A_DIM) * 4;                // 70656
    const int smem_y     = (A_DIM * C + YNB * A_DIM + C) * 4;              // <= 60 KB
    const int smem_mega  = (smem_fused > smem_y) ? smem_fused : smem_y;

    cudaFuncSetAttribute(k_mega, cudaFuncAttributeMaxDynamicSharedMemorySize, smem_mega);

    dim3 wtgrid(4, 4);
    k_wt<<<wtgrid, 256>>>(W, C);                       // also zeroes g_ccount
    k_labels<<<16, 128>>>(lraw, N, out, writeLoss);
    k_mega<<<YB + S, 256, smem_mega>>>(sigma, W, F, mu, bias, yout,
                                       C, K, N, YB);
    if (writeLoss)
        k_loss<<<(N + 7) / 8, 256>>>(yout, ratio, out, N, C, K);
}

// round 16
// speedup vs baseline: 1.0989x; 1.0730x over previous
#include <cuda_runtime.h>
#include <math.h>

// ISDALoss_EM on GB300 — round 16: mega-kernel with fused blocks FIRST
// (single-wave for the 400 sigma blocks), y-GEMM blocks last (absorbed into
// freed slots). Everything else byte-identical to round 15.
#define A_DIM 128
#define PITCH 132
#define MAX_S 512
#define MAX_N 4096
#define MAX_C 128

__device__ float g_WT[A_DIM * A_DIM];     // WT[i][c] = W[c][i]; c >= C zeroed
__device__ float g_D[MAX_S * A_DIM];
__device__ float g_U[MAX_S * A_DIM];
__device__ float g_score[MAX_N * 8];
__device__ int   g_labels[MAX_N];
__device__ int   g_ccount[MAX_C];
__device__ int   g_clist[(size_t)MAX_C * MAX_N];

__device__ __forceinline__ void fma2(unsigned long long& d, unsigned long long a,
                                     unsigned long long b) {
    asm("fma.rn.f32x2 %0, %1, %2, %0;" : "+l"(d) : "l"(a), "l"(b));
}
__device__ __forceinline__ unsigned long long pack2(float lo, float hi) {
    unsigned long long r;
    asm("mov.b64 %0, {%1,%2};" : "=l"(r) : "f"(lo), "f"(hi));
    return r;
}
__device__ __forceinline__ float2 unpack2(unsigned long long v) {
    float2 f;
    asm("mov.b64 {%0,%1}, %2;" : "=f"(f.x), "=f"(f.y) : "l"(v));
    return f;
}

// ---- W transpose (coalesced both ways) + zero g_ccount for k_labels --------
__global__ void k_wt(const float* __restrict__ W, int C) {
    __shared__ float tile[32][33];
    if (blockIdx.x == 0 && blockIdx.y == 0 && threadIdx.x < MAX_C)
        g_ccount[threadIdx.x] = 0;
    const int ct0 = blockIdx.x * 32;
    const int it0 = blockIdx.y * 32;
    const int tid = threadIdx.x;
    const int tr = tid >> 5, tc = tid & 31;
    #pragma unroll
    for (int r = 0; r < 32; r += 8) {
        int c = ct0 + tr + r;
        tile[tr + r][tc] = (c < C) ? W[(size_t)c * A_DIM + it0 + tc] : 0.0f;
    }
    __syncthreads();
    #pragma unroll
    for (int r = 0; r < 32; r += 8) {
        int i = it0 + tr + r;
        g_WT[(size_t)i * A_DIM + ct0 + tc] = tile[tc][tr + r];
    }
}

// labels: gridded; redundant detect for consistent dtype verdict.
__global__ void k_labels(const int* __restrict__ raw, int n,
                         float* out, int writeLoss) {
    const int tid = threadIdx.x;
    if (blockIdx.x == 0 && tid == 0 && writeLoss) out[0] = 0.0f;
    int nz = 0;
    for (int i = tid; i < n / 2; i += blockDim.x)
        nz |= (raw[2 * i + 1] != 0);
    const bool is32 = (__syncthreads_or(nz) != 0);
    const int stride = gridDim.x * blockDim.x;
    for (int i = blockIdx.x * blockDim.x + tid; i < n; i += stride) {
        int c = is32 ? raw[i] : raw[2 * i];
        g_labels[i] = c;
        int p = atomicAdd(&g_ccount[c], 1);
        g_clist[(size_t)c * MAX_N + p] = i;
    }
}

// ---- mega: fused sigma blocks (idx < S) + y-GEMM blocks (idx >= S) ----------
#define YNB 16
__global__ __launch_bounds__(256, 3)
void k_mega(const float* __restrict__ sigma, const float* __restrict__ W,
            const float* __restrict__ F, const float* __restrict__ mu,
            const float* __restrict__ bias, float* __restrict__ yout,
            int C, int K, int N, int S) {
    extern __shared__ float sh[];
    const int tid = threadIdx.x;
    const int wid = tid >> 5, lane = tid & 31;

    if (blockIdx.x >= S) {
        // ================= y-GEMM block: y = F W^T + b for 16 samples ========
        float* sWT = sh;                    // [128][C]
        float* sF  = sWT + A_DIM * C;       // [YNB][128]
        float* sB  = sF + YNB * A_DIM;      // [C]
        const int n0 = (blockIdx.x - S) * YNB;

        for (int idx = tid; idx < C * A_DIM; idx += 256) {
            int c = idx >> 7, aa = idx & 127;
            sWT[aa * C + c] = W[idx];
        }
        for (int idx = tid; idx < YNB * A_DIM; idx += 256) {
            int nl = idx >> 7;
            int n = n0 + nl;
            sF[idx] = (n < N) ? F[(size_t)n * A_DIM + (idx & 127)] : 0.0f;
        }
        for (int c = tid; c < C; c += 256) sB[c] = bias[c];
        __syncthreads();

        const int nchunk = (C + 31) >> 5;
        for (int task = wid; task < YNB * nchunk; task += 8) {
            int nl = task / nchunk;
            int c = (task - nl * nchunk) * 32 + lane;
            int n = n0 + nl;
            if (c < C && n < N) {
                float acc = sB[c];
                const float* f = sF + nl * A_DIM;
                #pragma unroll 1
                for (int aa = 0; aa < A_DIM; aa += 16) {
                    #pragma unroll
                    for (int q = 0; q < 16; q += 4) {
                        float4 fv = *reinterpret_cast<const float4*>(f + aa + q);
                        acc += fv.x * sWT[(aa + q) * C + c];
                        acc += fv.y * sWT[(aa + q + 1) * C + c];
                        acc += fv.z * sWT[(aa + q + 2) * C + c];
                        acc += fv.w * sWT[(aa + q + 3) * C + c];
                    }
                }
                yout[(size_t)n * C + c] = acc;
            }
        }
        return;
    }

    // ================= fused sigma block (byte-identical math) ===============
    float* sA  = sh;                       // 128 * 132
    float* swl = sA + A_DIM * PITCH;       // 128
    float* sv  = swl + A_DIM;              // 128
    float* srd = sv + A_DIM;               // 128
    float* sdg = srd + A_DIM;              // 128
    float* sD  = sdg + A_DIM;              // 128
    float* sU  = sD + A_DIM;               // 128
    __shared__ float slogdet;

    const int s = blockIdx.x;
    const int cls = s / K;
    const int kk = s - cls * K;

    // ---- load Sigma (float4, coalesced), w_l; zero sD ----
    {
        const float4* src4 = reinterpret_cast<const float4*>(sigma + (size_t)s * A_DIM * A_DIM);
        for (int idx = tid; idx < A_DIM * 32; idx += 256) {
            int i = idx >> 5, f = idx & 31;
            *reinterpret_cast<float4*>(&sA[i * PITCH + 4 * f]) = src4[idx];
        }
        if (tid < A_DIM) { swl[tid] = W[cls * A_DIM + tid]; sD[tid] = 0.0f; }
    }
    __syncthreads();

    // ---- v = Sigma @ w_l (before factorization) ----
    if (tid < A_DIM) {
        float acc = 0.0f;
        #pragma unroll 8
        for (int b = 0; b < A_DIM; ++b) acc += sA[b * PITCH + tid] * swl[b];
        sv[tid] = acc;
    }
    __syncthreads();

    // ---- blocked Cholesky (NB = 32) ----
    for (int kb = 0; kb < A_DIM; kb += 32) {
        if (wid == 0) {
            float m[32];
            float* row = &sA[(kb + lane) * PITCH + kb];
            #pragma unroll
            for (int c = 0; c < 32; ++c) m[c] = row[c];
            #pragma unroll
            for (int j = 0; j < 32; ++j) {
                float dj = __shfl_sync(0xffffffffu, m[j], j);
                float l = m[j] * rsqrtf(dj);
                m[j] = l;
                #pragma unroll
                for (int p = j + 1; p < 32; ++p)
                    m[p] -= l * __shfl_sync(0xffffffffu, l, p);
            }
            #pragma unroll
            for (int c = 0; c < 32; ++c)
                if (c <= lane) row[c] = m[c];
            srd[kb + lane] = 1.0f / m[lane];
            sdg[kb + lane] = m[lane];
        }
        __syncthreads();

        const int R = A_DIM - kb - 32;
        if (R > 0) {
            if (tid < R) {
                const int row = kb + 32 + tid;
                float* pr = &sA[row * PITCH + kb];
                const float* pd = &sA[kb * PITCH + kb];
                float x[32];
                #pragma unroll
                for (int c = 0; c < 32; ++c) x[c] = pr[c];
                #pragma unroll
                for (int j = 0; j < 32; ++j) {
                    float a = x[j];
                    #pragma unroll
                    for (int p = 0; p < j; ++p) a -= x[p] * pd[j * PITCH + p];
                    x[j] = a * srd[kb + j];
                }
                #pragma unroll
                for (int c = 0; c < 32; ++c) pr[c] = x[c];
            }
            __syncthreads();

            // SYRK: A22 -= L21 L21^T (lower), 8-col strips
            const int nb = R >> 5;
            const int ntask = 2 * nb * (nb + 1);
            for (int task = wid; task < ntask; task += 8) {
                int b = 0, t = task;
                while (t >= 4 * (b + 1)) { t -= 4 * (b + 1); ++b; }
                const int i  = kb + 32 + 32 * b + lane;
                const int j0 = kb + 32 + 8 * t;
                unsigned long long acc[8];
                #pragma unroll
                for (int q = 0; q < 8; ++q) acc[q] = 0ull;
                const float* pa = &sA[i * PITCH + kb];
                #pragma unroll
                for (int k = 0; k < 32; k += 4) {
                    ulonglong2 av = *reinterpret_cast<const ulonglong2*>(pa + k);
                    #pragma unroll
                    for (int q = 0; q < 8; ++q) {
                        ulonglong2 bv = *reinterpret_cast<const ulonglong2*>(
                            &sA[(j0 + q) * PITCH + kb + k]);
                        fma2(acc[q], av.x, bv.x);
                        fma2(acc[q], av.y, bv.y);
                    }
                }
                #pragma unroll
                for (int q = 0; q < 8; ++q) {
                    int col = j0 + q;
                    if (col <= i) {
                        float2 f = unpack2(acc[q]);
                        sA[i * PITCH + col] -= f.x + f.y;
                    }
                }
            }
            __syncthreads();
        }
    }

    // ---- zero upper triangle; logdet ----
    for (int idx = tid; idx < A_DIM * A_DIM; idx += 256) {
        int j = idx >> 7, i = idx & 127;
        if (i < j) sA[i * PITCH + j] = 0.0f;
    }
    if (tid < 32) {
        float v = logf(sdg[tid]) + logf(sdg[tid + 32]) +
                  logf(sdg[tid + 64]) + logf(sdg[tid + 96]);
        #pragma unroll
        for (int o = 16; o; o >>= 1) v += __shfl_xor_sync(0xffffffffu, v, o);
        if (tid == 0) slogdet = 2.0f * v;
    }
    __syncthreads();

    // ---- D_c = ||L^T w_c||^2, U_c = v . w_c ----
    for (int g = 0; g < 4; ++g) {
        const int t = (g & 1) ? (7 - wid) : wid;
        const int j0 = 16 * t;
        const int c = 32 * g + lane;
        unsigned long long acc[8];
        #pragma unroll
        for (int q = 0; q < 8; ++q) acc[q] = 0ull;
        float u = 0.0f;
        const bool doU = (t == 0);
        const float* wcol = g_WT + c;

        for (int i = j0; i < A_DIM; ++i) {
            const ulonglong2* Lr = reinterpret_cast<const ulonglong2*>(&sA[i * PITCH + j0]);
            ulonglong2 p0 = Lr[0];
            ulonglong2 p1 = Lr[1];
            ulonglong2 p2 = Lr[2];
            ulonglong2 p3 = Lr[3];
            float wv = wcol[i * A_DIM];
            unsigned long long w2 = pack2(wv, wv);
            fma2(acc[0], p0.x, w2);
            fma2(acc[1], p0.y, w2);
            fma2(acc[2], p1.x, w2);
            fma2(acc[3], p1.y, w2);
            fma2(acc[4], p2.x, w2);
            fma2(acc[5], p2.y, w2);
            fma2(acc[6], p3.x, w2);
            fma2(acc[7], p3.y, w2);
            if (doU) u += sv[i] * wv;
        }
        unsigned long long d2 = 0ull;
        #pragma unroll
        for (int q = 0; q < 8; ++q) fma2(d2, acc[q], acc[q]);
        float2 dd = unpack2(d2);
        atomicAdd(&sD[c], dd.x + dd.y);
        if (doU) sU[c] = u;
    }
    __syncthreads();

    for (int c = tid; c < C; c += 256) {
        g_D[s * A_DIM + c] = sD[c];
        g_U[s * A_DIM + c] = sU[c];
    }

    // ---- transpose lower -> upper (stale lower is dead in the solve) ----
    for (int idx = tid; idx < A_DIM * A_DIM; idx += 256) {
        int i = idx >> 7, j = idx & 127;
        if (i > j) sA[j * PITCH + i] = sA[i * PITCH + j];
    }
    __syncthreads();

    // ---- class-grouped solves: score = dist + logdet, 4 samples per warp ----
    const int cnt = g_ccount[cls];
    const float logd = slogdet;
    const float4* F4 = reinterpret_cast<const float4*>(F);
    const float4 mv = reinterpret_cast<const float4*>(mu)[(size_t)s * 32 + lane];

    for (int m0 = wid * 4; m0 < cnt; m0 += 32) {
        int n[4];
        bool has[4];
        #pragma unroll
        for (int r = 0; r < 4; ++r) {
            has[r] = (m0 + r) < cnt;
            n[r] = g_clist[(size_t)cls * MAX_N + (has[r] ? (m0 + r) : m0)];
        }
        float d[4][4], dist[4];
        #pragma unroll
        for (int r = 0; r < 4; ++r) {
            float4 fv = F4[(size_t)n[r] * 32 + lane];
            d[r][0] = fv.x - mv.x; d[r][1] = fv.y - mv.y;
            d[r][2] = fv.z - mv.z; d[r][3] = fv.w - mv.w;
            dist[r] = 0.0f;
        }
        #pragma unroll 4
        for (int j = 0; j < A_DIM; ++j) {
            float4 col = *reinterpret_cast<const float4*>(&sA[j * PITCH + 4 * lane]);
            float rdj = srd[j];
            int owner = j >> 2, q = j & 3;
            #pragma unroll
            for (int r = 0; r < 4; ++r) {
                float dq = (q == 0) ? d[r][0] : (q == 1) ? d[r][1]
                         : (q == 2) ? d[r][2] : d[r][3];
                float z = __shfl_sync(0xffffffffu, dq, owner) * rdj;
                dist[r] += z * z;
                d[r][0] -= col.x * z;
                d[r][1] -= col.y * z;
                d[r][2] -= col.z * z;
                d[r][3] -= col.w * z;
            }
        }
        if (lane == 0) {
            #pragma unroll
            for (int r = 0; r < 4; ++r)
                if (has[r]) g_score[n[r] * 8 + kk] = dist[r] + logd;
        }
    }
}

// ---- epilogue: per-sample argmin, aug, log-softmax, loss (warp per sample) --
__global__ __launch_bounds__(256)
void k_loss(const float* __restrict__ yv, const float* __restrict__ ratioPtr,
            float* __restrict__ lossout, int N, int C, int K) {
    const int warp = threadIdx.x >> 5, lane = threadIdx.x & 31;
    const int n = blockIdx.x * 8 + warp;
    if (n >= N) return;
    const float hr = 0.5f * ratioPtr[0];
    const int l = g_labels[n];
    const float* sc = g_score + n * 8;
    int k = 0;
    float best = sc[0];
    for (int kk = 1; kk < K; ++kk) {
        float v = sc[kk];
        if (v < best) { best = v; k = kk; }
    }
    const int s = l * K + k;
    const float* Dp = g_D + s * A_DIM;
    const float* Up = g_U + s * A_DIM;
    const float ul = Up[l];
    const float* yrow = yv + (size_t)n * C;
    const int nchunk = (C + 31) >> 5;

    float augv[4];
    float mymax = -INFINITY;
    #pragma unroll
    for (int m = 0; m < 4; ++m) {
        int c = lane + 32 * m;
        float v = -INFINITY;
        if (m < nchunk && c < C)
            v = yrow[c] + hr * (Dp[c] - 2.0f * Up[c] + ul);
        augv[m] = v;
        mymax = fmaxf(mymax, v);
    }
    #pragma unroll
    for (int o = 16; o; o >>= 1)
        mymax = fmaxf(mymax, __shfl_xor_sync(0xffffffffu, mymax, o));
    float sum = 0.0f;
    #pragma unroll
    for (int m = 0; m < 4; ++m) {
        int c = lane + 32 * m;
        if (m < nchunk && c < C) sum += expf(augv[m] - mymax);
    }
    #pragma unroll
    for (int o = 16; o; o >>= 1) sum += __shfl_xor_sync(0xffffffffu, sum, o);
    if (lane == 0) {
        float lse = mymax + logf(sum);
        float aug_l = yrow[l] + hr * (Dp[l] - Up[l]);
        atomicAdd(lossout, (lse - aug_l) / (float)N);
    }
}

// ---------------- launch -----------------------------------------------------
extern "C" void kernel_launch(void* const* d_in, const int* in_sizes, int n_in,
                              void* d_out, int out_size) {
    const float* F     = (const float*)d_in[0];
    const float* W     = (const float*)d_in[1];
    const float* bias  = (const float*)d_in[2];
    const float* mu    = (const float*)d_in[4];
    const float* sigma = (const float*)d_in[5];
    const int*   lraw  = (const int*)d_in[6];
    const float* ratio = (const float*)d_in[7];

    const int C = in_sizes[2];
    const int K = in_sizes[3] / C;
    const int Ad = in_sizes[1] / C;
    const int N = in_sizes[0] / Ad;
    const int S = C * K;
    const int YB = (N + YNB - 1) / YNB;

    float* out = (float*)d_out;
    const int yoff = out_size - N * C;
    const int writeLoss = (yoff >= 1) ? 1 : 0;
    float* yout = out + (yoff > 0 ? yoff : 0);

    const int smem_fused = (A_DIM * PITCH + 6 * A_DIM) * 4;                // 70656
    const int smem_y     = (A_DIM * C + YNB * A_DIM + C) * 4;              // <= 60 KB
    const int smem_mega  = (smem_fused > smem_y) ? smem_fused : smem_y;

    cudaFuncSetAttribute(k_mega, cudaFuncAttributeMaxDynamicSharedMemorySize, smem_mega);

    dim3 wtgrid(4, 4);
    k_wt<<<wtgrid, 256>>>(W, C);                       // also zeroes g_ccount
    k_labels<<<16, 128>>>(lraw, N, out, writeLoss);
    k_mega<<<S + YB, 256, smem_mega>>>(sigma, W, F, mu, bias, yout,
                                       C, K, N, S);
    if (writeLoss)
        k_loss<<<(N + 7) / 8, 256>>>(yout, ratio, out, N, C, K);
}

// round 17
// speedup vs baseline: 1.1356x; 1.0334x over previous
#include <cuda_runtime.h>
#include <math.h>

// ISDALoss_EM on GB300 — round 17: k_loss two-stage reduction (kills the
// single-address atomic serialization); mega zeroes only the D/U ramp
// triangles instead of the whole upper half. Otherwise byte-identical.
#define A_DIM 128
#define PITCH 132
#define MAX_S 512
#define MAX_N 4096
#define MAX_C 128

__device__ float g_WT[A_DIM * A_DIM];     // WT[i][c] = W[c][i]; c >= C zeroed
__device__ float g_D[MAX_S * A_DIM];
__device__ float g_U[MAX_S * A_DIM];
__device__ float g_score[MAX_N * 8];
__device__ int   g_labels[MAX_N];
__device__ int   g_ccount[MAX_C];
__device__ int   g_clist[(size_t)MAX_C * MAX_N];

__device__ __forceinline__ void fma2(unsigned long long& d, unsigned long long a,
                                     unsigned long long b) {
    asm("fma.rn.f32x2 %0, %1, %2, %0;" : "+l"(d) : "l"(a), "l"(b));
}
__device__ __forceinline__ unsigned long long pack2(float lo, float hi) {
    unsigned long long r;
    asm("mov.b64 %0, {%1,%2};" : "=l"(r) : "f"(lo), "f"(hi));
    return r;
}
__device__ __forceinline__ float2 unpack2(unsigned long long v) {
    float2 f;
    asm("mov.b64 {%0,%1}, %2;" : "=f"(f.x), "=f"(f.y) : "l"(v));
    return f;
}

// ---- W transpose (coalesced both ways) + zero g_ccount for k_labels --------
__global__ void k_wt(const float* __restrict__ W, int C) {
    __shared__ float tile[32][33];
    if (blockIdx.x == 0 && blockIdx.y == 0 && threadIdx.x < MAX_C)
        g_ccount[threadIdx.x] = 0;
    const int ct0 = blockIdx.x * 32;
    const int it0 = blockIdx.y * 32;
    const int tid = threadIdx.x;
    const int tr = tid >> 5, tc = tid & 31;
    #pragma unroll
    for (int r = 0; r < 32; r += 8) {
        int c = ct0 + tr + r;
        tile[tr + r][tc] = (c < C) ? W[(size_t)c * A_DIM + it0 + tc] : 0.0f;
    }
    __syncthreads();
    #pragma unroll
    for (int r = 0; r < 32; r += 8) {
        int i = it0 + tr + r;
        g_WT[(size_t)i * A_DIM + ct0 + tc] = tile[tc][tr + r];
    }
}

// labels: gridded; redundant detect for consistent dtype verdict.
__global__ void k_labels(const int* __restrict__ raw, int n,
                         float* out, int writeLoss) {
    const int tid = threadIdx.x;
    if (blockIdx.x == 0 && tid == 0 && writeLoss) out[0] = 0.0f;
    int nz = 0;
    for (int i = tid; i < n / 2; i += blockDim.x)
        nz |= (raw[2 * i + 1] != 0);
    const bool is32 = (__syncthreads_or(nz) != 0);
    const int stride = gridDim.x * blockDim.x;
    for (int i = blockIdx.x * blockDim.x + tid; i < n; i += stride) {
        int c = is32 ? raw[i] : raw[2 * i];
        g_labels[i] = c;
        int p = atomicAdd(&g_ccount[c], 1);
        g_clist[(size_t)c * MAX_N + p] = i;
    }
}

// ---- mega: fused sigma blocks (idx < S) + y-GEMM blocks (idx >= S) ----------
#define YNB 16
__global__ __launch_bounds__(256, 3)
void k_mega(const float* __restrict__ sigma, const float* __restrict__ W,
            const float* __restrict__ F, const float* __restrict__ mu,
            const float* __restrict__ bias, float* __restrict__ yout,
            int C, int K, int N, int S) {
    extern __shared__ float sh[];
    const int tid = threadIdx.x;
    const int wid = tid >> 5, lane = tid & 31;

    if (blockIdx.x >= S) {
        // ================= y-GEMM block: y = F W^T + b for 16 samples ========
        float* sWT = sh;                    // [128][C]
        float* sF  = sWT + A_DIM * C;       // [YNB][128]
        float* sB  = sF + YNB * A_DIM;      // [C]
        const int n0 = (blockIdx.x - S) * YNB;

        for (int idx = tid; idx < C * A_DIM; idx += 256) {
            int c = idx >> 7, aa = idx & 127;
            sWT[aa * C + c] = W[idx];
        }
        for (int idx = tid; idx < YNB * A_DIM; idx += 256) {
            int nl = idx >> 7;
            int n = n0 + nl;
            sF[idx] = (n < N) ? F[(size_t)n * A_DIM + (idx & 127)] : 0.0f;
        }
        for (int c = tid; c < C; c += 256) sB[c] = bias[c];
        __syncthreads();

        const int nchunk = (C + 31) >> 5;
        for (int task = wid; task < YNB * nchunk; task += 8) {
            int nl = task / nchunk;
            int c = (task - nl * nchunk) * 32 + lane;
            int n = n0 + nl;
            if (c < C && n < N) {
                float acc = sB[c];
                const float* f = sF + nl * A_DIM;
                #pragma unroll 1
                for (int aa = 0; aa < A_DIM; aa += 16) {
                    #pragma unroll
                    for (int q = 0; q < 16; q += 4) {
                        float4 fv = *reinterpret_cast<const float4*>(f + aa + q);
                        acc += fv.x * sWT[(aa + q) * C + c];
                        acc += fv.y * sWT[(aa + q + 1) * C + c];
                        acc += fv.z * sWT[(aa + q + 2) * C + c];
                        acc += fv.w * sWT[(aa + q + 3) * C + c];
                    }
                }
                yout[(size_t)n * C + c] = acc;
            }
        }
        return;
    }

    // ================= fused sigma block ====================================
    float* sA  = sh;                       // 128 * 132
    float* swl = sA + A_DIM * PITCH;       // 128
    float* sv  = swl + A_DIM;              // 128
    float* srd = sv + A_DIM;               // 128
    float* sdg = srd + A_DIM;              // 128
    float* sD  = sdg + A_DIM;              // 128
    float* sU  = sD + A_DIM;               // 128
    __shared__ float slogdet;

    const int s = blockIdx.x;
    const int cls = s / K;
    const int kk = s - cls * K;

    // ---- load Sigma (float4, coalesced), w_l; zero sD ----
    {
        const float4* src4 = reinterpret_cast<const float4*>(sigma + (size_t)s * A_DIM * A_DIM);
        for (int idx = tid; idx < A_DIM * 32; idx += 256) {
            int i = idx >> 5, f = idx & 31;
            *reinterpret_cast<float4*>(&sA[i * PITCH + 4 * f]) = src4[idx];
        }
        if (tid < A_DIM) { swl[tid] = W[cls * A_DIM + tid]; sD[tid] = 0.0f; }
    }
    __syncthreads();

    // ---- v = Sigma @ w_l (before factorization) ----
    if (tid < A_DIM) {
        float acc = 0.0f;
        #pragma unroll 8
        for (int b = 0; b < A_DIM; ++b) acc += sA[b * PITCH + tid] * swl[b];
        sv[tid] = acc;
    }
    __syncthreads();

    // ---- blocked Cholesky (NB = 32) ----
    for (int kb = 0; kb < A_DIM; kb += 32) {
        if (wid == 0) {
            float m[32];
            float* row = &sA[(kb + lane) * PITCH + kb];
            #pragma unroll
            for (int c = 0; c < 32; ++c) m[c] = row[c];
            #pragma unroll
            for (int j = 0; j < 32; ++j) {
                float dj = __shfl_sync(0xffffffffu, m[j], j);
                float l = m[j] * rsqrtf(dj);
                m[j] = l;
                #pragma unroll
                for (int p = j + 1; p < 32; ++p)
                    m[p] -= l * __shfl_sync(0xffffffffu, l, p);
            }
            #pragma unroll
            for (int c = 0; c < 32; ++c)
                if (c <= lane) row[c] = m[c];
            srd[kb + lane] = 1.0f / m[lane];
            sdg[kb + lane] = m[lane];
        }
        __syncthreads();

        const int R = A_DIM - kb - 32;
        if (R > 0) {
            if (tid < R) {
                const int row = kb + 32 + tid;
                float* pr = &sA[row * PITCH + kb];
                const float* pd = &sA[kb * PITCH + kb];
                float x[32];
                #pragma unroll
                for (int c = 0; c < 32; ++c) x[c] = pr[c];
                #pragma unroll
                for (int j = 0; j < 32; ++j) {
                    float a = x[j];
                    #pragma unroll
                    for (int p = 0; p < j; ++p) a -= x[p] * pd[j * PITCH + p];
                    x[j] = a * srd[kb + j];
                }
                #pragma unroll
                for (int c = 0; c < 32; ++c) pr[c] = x[c];
            }
            __syncthreads();

            // SYRK: A22 -= L21 L21^T (lower), 8-col strips
            const int nb = R >> 5;
            const int ntask = 2 * nb * (nb + 1);
            for (int task = wid; task < ntask; task += 8) {
                int b = 0, t = task;
                while (t >= 4 * (b + 1)) { t -= 4 * (b + 1); ++b; }
                const int i  = kb + 32 + 32 * b + lane;
                const int j0 = kb + 32 + 8 * t;
                unsigned long long acc[8];
                #pragma unroll
                for (int q = 0; q < 8; ++q) acc[q] = 0ull;
                const float* pa = &sA[i * PITCH + kb];
                #pragma unroll
                for (int k = 0; k < 32; k += 4) {
                    ulonglong2 av = *reinterpret_cast<const ulonglong2*>(pa + k);
                    #pragma unroll
                    for (int q = 0; q < 8; ++q) {
                        ulonglong2 bv = *reinterpret_cast<const ulonglong2*>(
                            &sA[(j0 + q) * PITCH + kb + k]);
                        fma2(acc[q], av.x, bv.x);
                        fma2(acc[q], av.y, bv.y);
                    }
                }
                #pragma unroll
                for (int q = 0; q < 8; ++q) {
                    int col = j0 + q;
                    if (col <= i) {
                        float2 f = unpack2(acc[q]);
                        sA[i * PITCH + col] -= f.x + f.y;
                    }
                }
            }
            __syncthreads();
        }
    }

    // ---- zero ONLY the 16x16 ramp triangles read by the D/U strips; the rest
    //      of the upper half is overwritten by the transpose before the solve.
    {
        const int j0 = wid * 16;
        for (int e = lane; e < 120; e += 32) {
            int r = 0, t = e;
            while (t >= 15 - r) { t -= 15 - r; ++r; }
            int cc = r + 1 + t;               // strict upper: col > row
            sA[(j0 + r) * PITCH + (j0 + cc)] = 0.0f;
        }
    }
    if (tid < 32) {
        float v = logf(sdg[tid]) + logf(sdg[tid + 32]) +
                  logf(sdg[tid + 64]) + logf(sdg[tid + 96]);
        #pragma unroll
        for (int o = 16; o; o >>= 1) v += __shfl_xor_sync(0xffffffffu, v, o);
        if (tid == 0) slogdet = 2.0f * v;
    }
    __syncthreads();

    // ---- D_c = ||L^T w_c||^2, U_c = v . w_c ----
    for (int g = 0; g < 4; ++g) {
        const int t = (g & 1) ? (7 - wid) : wid;
        const int j0 = 16 * t;
        const int c = 32 * g + lane;
        unsigned long long acc[8];
        #pragma unroll
        for (int q = 0; q < 8; ++q) acc[q] = 0ull;
        float u = 0.0f;
        const bool doU = (t == 0);
        const float* wcol = g_WT + c;

        for (int i = j0; i < A_DIM; ++i) {
            const ulonglong2* Lr = reinterpret_cast<const ulonglong2*>(&sA[i * PITCH + j0]);
            ulonglong2 p0 = Lr[0];
            ulonglong2 p1 = Lr[1];
            ulonglong2 p2 = Lr[2];
            ulonglong2 p3 = Lr[3];
            float wv = wcol[i * A_DIM];
            unsigned long long w2 = pack2(wv, wv);
            fma2(acc[0], p0.x, w2);
            fma2(acc[1], p0.y, w2);
            fma2(acc[2], p1.x, w2);
            fma2(acc[3], p1.y, w2);
            fma2(acc[4], p2.x, w2);
            fma2(acc[5], p2.y, w2);
            fma2(acc[6], p3.x, w2);
            fma2(acc[7], p3.y, w2);
            if (doU) u += sv[i] * wv;
        }
        unsigned long long d2 = 0ull;
        #pragma unroll
        for (int q = 0; q < 8; ++q) fma2(d2, acc[q], acc[q]);
        float2 dd = unpack2(d2);
        atomicAdd(&sD[c], dd.x + dd.y);
        if (doU) sU[c] = u;
    }
    __syncthreads();

    for (int c = tid; c < C; c += 256) {
        g_D[s * A_DIM + c] = sD[c];
        g_U[s * A_DIM + c] = sU[c];
    }

    // ---- transpose lower -> upper (writes every strict-upper entry) ----
    for (int idx = tid; idx < A_DIM * A_DIM; idx += 256) {
        int i = idx >> 7, j = idx & 127;
        if (i > j) sA[j * PITCH + i] = sA[i * PITCH + j];
    }
    __syncthreads();

    // ---- class-grouped solves: score = dist + logdet, 4 samples per warp ----
    const int cnt = g_ccount[cls];
    const float logd = slogdet;
    const float4* F4 = reinterpret_cast<const float4*>(F);
    const float4 mv = reinterpret_cast<const float4*>(mu)[(size_t)s * 32 + lane];

    for (int m0 = wid * 4; m0 < cnt; m0 += 32) {
        int n[4];
        bool has[4];
        #pragma unroll
        for (int r = 0; r < 4; ++r) {
            has[r] = (m0 + r) < cnt;
            n[r] = g_clist[(size_t)cls * MAX_N + (has[r] ? (m0 + r) : m0)];
        }
        float d[4][4], dist[4];
        #pragma unroll
        for (int r = 0; r < 4; ++r) {
            float4 fv = F4[(size_t)n[r] * 32 + lane];
            d[r][0] = fv.x - mv.x; d[r][1] = fv.y - mv.y;
            d[r][2] = fv.z - mv.z; d[r][3] = fv.w - mv.w;
            dist[r] = 0.0f;
        }
        #pragma unroll 4
        for (int j = 0; j < A_DIM; ++j) {
            float4 col = *reinterpret_cast<const float4*>(&sA[j * PITCH + 4 * lane]);
            float rdj = srd[j];
            int owner = j >> 2, q = j & 3;
            #pragma unroll
            for (int r = 0; r < 4; ++r) {
                float dq = (q == 0) ? d[r][0] : (q == 1) ? d[r][1]
                         : (q == 2) ? d[r][2] : d[r][3];
                float z = __shfl_sync(0xffffffffu, dq, owner) * rdj;
                dist[r] += z * z;
                d[r][0] -= col.x * z;
                d[r][1] -= col.y * z;
                d[r][2] -= col.z * z;
                d[r][3] -= col.w * z;
            }
        }
        if (lane == 0) {
            #pragma unroll
            for (int r = 0; r < 4; ++r)
                if (has[r]) g_score[n[r] * 8 + kk] = dist[r] + logd;
        }
    }
}

// ---- epilogue: argmin, aug, log-softmax, loss. Block-level partial sums ----
__global__ __launch_bounds__(256)
void k_loss(const float* __restrict__ yv, const float* __restrict__ ratioPtr,
            float* __restrict__ lossout, int N, int C, int K) {
    __shared__ float spart[8];
    const int warp = threadIdx.x >> 5, lane = threadIdx.x & 31;
    const int n = blockIdx.x * 8 + warp;
    float part = 0.0f;
    if (n < N) {
        const float hr = 0.5f * ratioPtr[0];
        const int l = g_labels[n];
        const float* sc = g_score + n * 8;
        int k = 0;
        float best = sc[0];
        for (int kk = 1; kk < K; ++kk) {
            float v = sc[kk];
            if (v < best) { best = v; k = kk; }
        }
        const int s = l * K + k;
        const float* Dp = g_D + s * A_DIM;
        const float* Up = g_U + s * A_DIM;
        const float ul = Up[l];
        const float* yrow = yv + (size_t)n * C;
        const int nchunk = (C + 31) >> 5;

        float augv[4];
        float mymax = -INFINITY;
        #pragma unroll
        for (int m = 0; m < 4; ++m) {
            int c = lane + 32 * m;
            float v = -INFINITY;
            if (m < nchunk && c < C)
                v = yrow[c] + hr * (Dp[c] - 2.0f * Up[c] + ul);
            augv[m] = v;
            mymax = fmaxf(mymax, v);
        }
        #pragma unroll
        for (int o = 16; o; o >>= 1)
            mymax = fmaxf(mymax, __shfl_xor_sync(0xffffffffu, mymax, o));
        float sum = 0.0f;
        #pragma unroll
        for (int m = 0; m < 4; ++m) {
            int c = lane + 32 * m;
            if (m < nchunk && c < C) sum += expf(augv[m] - mymax);
        }
        #pragma unroll
        for (int o = 16; o; o >>= 1) sum += __shfl_xor_sync(0xffffffffu, sum, o);
        if (lane == 0) {
            float lse = mymax + logf(sum);
            float aug_l = yrow[l] + hr * (Dp[l] - Up[l]);
            part = (lse - aug_l) / (float)N;
        }
    }
    if (lane == 0) spart[warp] = part;
    __syncthreads();
    if (threadIdx.x == 0) {
        float t = spart[0] + spart[1] + spart[2] + spart[3]
                + spart[4] + spart[5] + spart[6] + spart[7];
        atomicAdd(lossout, t);
    }
}

// ---------------- launch -----------------------------------------------------
extern "C" void kernel_launch(void* const* d_in, const int* in_sizes, int n_in,
                              void* d_out, int out_size) {
    const float* F     = (const float*)d_in[0];
    const float* W     = (const float*)d_in[1];
    const float* bias  = (const float*)d_in[2];
    const float* mu    = (const float*)d_in[4];
    const float* sigma = (const float*)d_in[5];
    const int*   lraw  = (const int*)d_in[6];
    const float* ratio = (const float*)d_in[7];

    const int C = in_sizes[2];
    const int K = in_sizes[3] / C;
    const int Ad = in_sizes[1] / C;
    const int N = in_sizes[0] / Ad;
    const int S = C * K;
    const int YB = (N + YNB - 1) / YNB;

    float* out = (float*)d_out;
    const int yoff = out_size - N * C;
    const int writeLoss = (yoff >= 1) ? 1 : 0;
    float* yout = out + (yoff > 0 ? yoff : 0);

    const int smem_fused = (A_DIM * PITCH + 6 * A_DIM) * 4;                // 70656
    const int smem_y     = (A_DIM * C + YNB * A_DIM + C) * 4;              // <= 60 KB
    const int smem_mega  = (smem_fused > smem_y) ? smem_fused : smem_y;

    cudaFuncSetAttribute(k_mega, cudaFuncAttributeMaxDynamicSharedMemorySize, smem_mega);

    dim3 wtgrid(4, 4);
    k_wt<<<wtgrid, 256>>>(W, C);                       // also zeroes g_ccount
    k_labels<<<16, 128>>>(lraw, N, out, writeLoss);
    k_mega<<<S + YB, 256, smem_mega>>>(sigma, W, F, mu, bias, yout,
                                       C, K, N, S);
    if (writeLoss)
        k_loss<<<(N + 7) / 8, 256>>>(yout, ratio, out, N, C, K);
}